// round 14
// baseline (speedup 1.0000x reference)
#include <cuda_runtime.h>
#include <cuda_bf16.h>
#include <math.h>
#include <stdint.h>

// Problem constants
#define BATCH 4
#define SEQ   2048
#define EMB   1024
#define NH    16
#define HD    64
#define WIN   512

// Scratch (device globals; allocation is forbidden).
__device__ uint32_t g_q[(size_t)BATCH * NH * SEQ * HD];   // [B,H,S,D] tf32
__device__ uint32_t g_k[(size_t)BATCH * NH * SEQ * HD];
__device__ uint32_t g_v[(size_t)BATCH * NH * SEQ * HD];
__device__ uint32_t g_xa[(size_t)BATCH * SEQ * EMB];      // x in tf32
__device__ uint32_t g_wi[(size_t)3 * EMB * EMB];          // w_in in tf32
__device__ uint32_t g_wo[(size_t)EMB * EMB];              // w_out in tf32
__device__ uint32_t g_ot[(size_t)BATCH * SEQ * EMB];      // attn out tf32

__device__ __forceinline__ uint32_t f2tf(float x) {
    uint32_t r;
    asm("cvt.rna.tf32.f32 %0, %1;" : "=r"(r) : "f"(x));
    return r;
}
__device__ __forceinline__ uint4 cvt4(float4 v) {
    return make_uint4(f2tf(v.x), f2tf(v.y), f2tf(v.z), f2tf(v.w));
}

__global__ __launch_bounds__(256)
void to_tf32(const float* __restrict__ in, uint32_t* __restrict__ out, int n)
{
    int i = (blockIdx.x * blockDim.x + threadIdx.x) * 4;
    if (i < n) {
        float4 v = *(const float4*)(in + i);
        *(uint4*)(out + i) = cvt4(v);
    }
}

#define MMA_TF32(c, a, b0_, b1_)                                            \
    asm volatile(                                                           \
        "mma.sync.aligned.m16n8k8.row.col.f32.tf32.tf32.f32 "               \
        "{%0,%1,%2,%3}, {%4,%5,%6,%7}, {%8,%9}, {%0,%1,%2,%3};"            \
        : "+f"((c)[0]), "+f"((c)[1]), "+f"((c)[2]), "+f"((c)[3])            \
        : "r"((a)[0]), "r"((a)[1]), "r"((a)[2]), "r"((a)[3]),               \
          "r"(b0_), "r"(b1_))

// ---------------------------------------------------------------------------
// TF32 tensor-core GEMM (NT): C[M,N] = A[M,K] * B[N,K]^T, K=1024.
// Block tile 128x128, K-tile 32 (halves barrier count vs R13), 256 threads =
// 8 warps (4M x 2N), warp tile 32x64. 3-stage cp.async pipeline, dynamic smem
// (96KB). Smem layout [row][32 words] with chunk-XOR swizzle (chunk ^= row&7)
// -> all STS/LDS.128 conflict-free. k-permutation across slices is consistent
// between A and B, so the contraction is exact.
// ---------------------------------------------------------------------------
#define BM 128
#define BN 128
#define BKK 32
#define STG 3
#define GEMM_SMEM (STG * 2 * BM * BKK * 4)   // 98304 bytes

__device__ __forceinline__ void cp_async16(uint32_t saddr, const void* gptr) {
    asm volatile("cp.async.cg.shared.global [%0], [%1], 16;\n"
                 :: "r"(saddr), "l"(gptr));
}
#define CP_COMMIT() asm volatile("cp.async.commit_group;\n" ::: "memory")
#define CP_WAIT1()  asm volatile("cp.async.wait_group 1;\n" ::: "memory")

__device__ __forceinline__ int swz32(int row, int chunk) {
    return (row << 5) + ((chunk ^ (row & 7)) << 2);
}

__device__ __forceinline__ void gemm_mainloop(
    const uint32_t* __restrict__ Ag, const uint32_t* __restrict__ Bg,
    uint32_t* Asb, uint32_t* Bsb,            // flat [STG*128*32] each
    float acc[2][8][4],
    int tid, int warpM, int warpN, int g, int tg)
{
    const int K = EMB;
    const int NT = K / BKK;                  // 32
    const int lr = tid >> 3;                 // 0..31
    const int lc = tid & 7;                  // chunk 0..7
    const int lwo = (lr << 5) + ((lc ^ (lr & 7)) << 2);

    const uint32_t* Agp = Ag + (size_t)lr * K + lc * 4;
    const uint32_t* Bgp = Bg + (size_t)lr * K + lc * 4;

    uint32_t sa[STG], sb[STG];
#pragma unroll
    for (int s = 0; s < STG; s++) {
        sa[s] = (uint32_t)__cvta_generic_to_shared(Asb + s * (BM * BKK) + lwo);
        sb[s] = (uint32_t)__cvta_generic_to_shared(Bsb + s * (BM * BKK) + lwo);
    }

    // prologue: prefetch tiles 0 and 1
#pragma unroll
    for (int p = 0; p < 2; p++) {
#pragma unroll
        for (int i = 0; i < 4; i++) {
            cp_async16(sa[p] + i * 4096, Agp + (size_t)(32 * i) * K + p * BKK);
            cp_async16(sb[p] + i * 4096, Bgp + (size_t)(32 * i) * K + p * BKK);
        }
        CP_COMMIT();
    }

    int st = 0;
    for (int kt = 0; kt < NT; kt++) {
        CP_WAIT1();
        __syncthreads();

        if (kt + 2 < NT) {
            int sn = st + 2; if (sn >= STG) sn -= STG;
            int ko = (kt + 2) * BKK;
#pragma unroll
            for (int i = 0; i < 4; i++) {
                cp_async16(sa[sn] + i * 4096, Agp + (size_t)(32 * i) * K + ko);
                cp_async16(sb[sn] + i * 4096, Bgp + (size_t)(32 * i) * K + ko);
            }
        }
        CP_COMMIT();

        const uint32_t* Ast = Asb + st * (BM * BKK);
        const uint32_t* Bst = Bsb + st * (BM * BKK);
#pragma unroll
        for (int h = 0; h < 2; h++) {
            uint32_t ae[2][4], ao[2][4];
#pragma unroll
            for (int mt = 0; mt < 2; mt++) {
                int row = warpM * 32 + mt * 16 + g;
                uint4 va = *(const uint4*)(Ast + swz32(row, h * 4 + tg));
                uint4 vb = *(const uint4*)(Ast + swz32(row + 8, h * 4 + tg));
                ae[mt][0] = va.x; ae[mt][1] = vb.x;
                ae[mt][2] = va.y; ae[mt][3] = vb.y;
                ao[mt][0] = va.z; ao[mt][1] = vb.z;
                ao[mt][2] = va.w; ao[mt][3] = vb.w;
            }
#pragma unroll
            for (int nt = 0; nt < 8; nt++) {
                int col = warpN * 64 + nt * 8 + g;
                uint4 wv = *(const uint4*)(Bst + swz32(col, h * 4 + tg));
                MMA_TF32(acc[0][nt], ae[0], wv.x, wv.y);
                MMA_TF32(acc[1][nt], ae[1], wv.x, wv.y);
                MMA_TF32(acc[0][nt], ao[0], wv.z, wv.w);
                MMA_TF32(acc[1][nt], ao[1], wv.z, wv.w);
            }
        }
        st++; if (st >= STG) st = 0;
    }
}

// GEMM1: qkv projection; scatter tf32 bits into g_q/g_k/g_v ([B,H,S,D])
__global__ __launch_bounds__(256, 2)
void qkv_gemm(const uint32_t* __restrict__ A,
              const uint32_t* __restrict__ B)
{
    extern __shared__ uint32_t gsm[];
    uint32_t* Asb = gsm;
    uint32_t* Bsb = gsm + STG * BM * BKK;

    const int tid = threadIdx.x;
    const int m0 = blockIdx.y * BM;
    const int n0 = blockIdx.x * BN;
    const int warp = tid >> 5;
    const int warpM = warp >> 1;
    const int warpN = warp & 1;
    const int lane = tid & 31;
    const int g = lane >> 2;
    const int tg = lane & 3;

    float acc[2][8][4];
#pragma unroll
    for (int mt = 0; mt < 2; mt++)
#pragma unroll
        for (int nt = 0; nt < 8; nt++)
#pragma unroll
            for (int j = 0; j < 4; j++) acc[mt][nt][j] = 0.f;

    gemm_mainloop(A + (size_t)m0 * EMB, B + (size_t)n0 * EMB,
                  Asb, Bsb, acc, tid, warpM, warpN, g, tg);

#pragma unroll
    for (int nt = 0; nt < 8; nt++) {
        int f = n0 + warpN * 64 + nt * 8 + 2 * tg;
        int part = f >> 10;
        int e2 = f & 1023;
        int hh = e2 >> 6;
        int d0 = e2 & 63;
        uint32_t* base = (part == 0) ? g_q : (part == 1) ? g_k : g_v;
#pragma unroll
        for (int mt = 0; mt < 2; mt++) {
            int r0 = m0 + warpM * 32 + mt * 16 + g;
            {
                int bb = r0 >> 11;
                int ss = r0 & 2047;
                size_t off = ((((size_t)bb * NH + hh) * SEQ) + ss) * HD + d0;
                *(uint2*)(base + off) =
                    make_uint2(f2tf(acc[mt][nt][0]), f2tf(acc[mt][nt][1]));
            }
            {
                int r1 = r0 + 8;
                int bb = r1 >> 11;
                int ss = r1 & 2047;
                size_t off = ((((size_t)bb * NH + hh) * SEQ) + ss) * HD + d0;
                *(uint2*)(base + off) =
                    make_uint2(f2tf(acc[mt][nt][2]), f2tf(acc[mt][nt][3]));
            }
        }
    }
}

// GEMM2: output projection, plain row-major fp32 C
__global__ __launch_bounds__(256, 2)
void out_gemm(const uint32_t* __restrict__ A,
              const uint32_t* __restrict__ B,
              float* __restrict__ C)
{
    extern __shared__ uint32_t gsm[];
    uint32_t* Asb = gsm;
    uint32_t* Bsb = gsm + STG * BM * BKK;

    const int tid = threadIdx.x;
    const int m0 = blockIdx.y * BM;
    const int n0 = blockIdx.x * BN;
    const int warp = tid >> 5;
    const int warpM = warp >> 1;
    const int warpN = warp & 1;
    const int lane = tid & 31;
    const int g = lane >> 2;
    const int tg = lane & 3;

    float acc[2][8][4];
#pragma unroll
    for (int mt = 0; mt < 2; mt++)
#pragma unroll
        for (int nt = 0; nt < 8; nt++)
#pragma unroll
            for (int j = 0; j < 4; j++) acc[mt][nt][j] = 0.f;

    gemm_mainloop(A + (size_t)m0 * EMB, B + (size_t)n0 * EMB,
                  Asb, Bsb, acc, tid, warpM, warpN, g, tg);

#pragma unroll
    for (int nt = 0; nt < 8; nt++) {
        int f = n0 + warpN * 64 + nt * 8 + 2 * tg;
#pragma unroll
        for (int mt = 0; mt < 2; mt++) {
            int r0 = m0 + warpM * 32 + mt * 16 + g;
            *(float2*)(C + (size_t)r0 * EMB + f) =
                make_float2(acc[mt][nt][0], acc[mt][nt][1]);
            *(float2*)(C + (size_t)(r0 + 8) * EMB + f) =
                make_float2(acc[mt][nt][2], acc[mt][nt][3]);
        }
    }
}

// ---------------------------------------------------------------------------
// Tensor-core sliding-window attention with ALiBi.
// Grid (S/128, H, B), 256 threads = 8 warps; warp w owns q rows [16w,16w+16).
// KV tiles of 64. Fixed analytic softmax shift -> no online max/rescaling.
// NEW: per-warp tile skip — tiles entirely outside the warp's sliding window
// (all P == 0) skip score+softmax+PV compute (loads/barriers stay CTA-wide).
// ---------------------------------------------------------------------------
#define AQT 128
#define AKT 64

__device__ __forceinline__ int swz(int row, int chunk) {
    return (row << 6) + (((chunk) ^ ((row & 3) << 2)) << 2);
}

__global__ __launch_bounds__(256, 2)
void attn_tc()
{
    extern __shared__ uint32_t sm[];
    uint32_t* Ks = sm;             // [64][64] swizzled (kv-major)
    uint32_t* Vt = sm + 4096;      // [64][64] swizzled (d-major, transposed V)
    uint32_t* Ps = sm + 8192;      // [128][64] swizzled (per-warp 16-row slices)

    const int b = blockIdx.z, h = blockIdx.y;
    const int qs = blockIdx.x * AQT;
    const int t = threadIdx.x;
    const int w = t >> 5, lane = t & 31;
    const int g = lane >> 2, tg = lane & 3;
    const int wr = w * 16;

    const size_t head_off = (((size_t)b * NH + h) * SEQ) * HD;
    const uint32_t* Qg = g_q + head_off;
    const uint32_t* Kg = g_k + head_off;
    const uint32_t* Vg = g_v + head_off;

    uint4 qv[2][4];
    {
        const uint32_t* q0 = Qg + (size_t)(qs + wr + g) * HD + 4 * tg;
        const uint32_t* q1 = Qg + (size_t)(qs + wr + 8 + g) * HD + 4 * tg;
#pragma unroll
        for (int i = 0; i < 4; i++) {
            qv[0][i] = *(const uint4*)(q0 + 16 * i);
            qv[1][i] = *(const uint4*)(q1 + 16 * i);
        }
    }

    const float slope = exp2f(-(float)(h + 1) * 0.5f);
    const int row0 = qs + wr + g, row1 = row0 + 8;
    const float sh0 = slope * (float)((row0 < WIN) ? row0 : WIN);
    const float sh1 = slope * (float)((row1 < WIN) ? row1 : WIN);

    float oacc[8][4];
#pragma unroll
    for (int nt = 0; nt < 8; nt++)
#pragma unroll
        for (int j = 0; j < 4; j++) oacc[nt][j] = 0.f;
    float l0 = 0.f, l1 = 0.f;

    const int lo = (qs >= WIN) ? qs - WIN : 0;
    const int krow = t >> 2, kq = t & 3;
    const int vkv = t & 63, vdb = t >> 6;
    const int wmin = qs + wr;          // warp's min q row
    const int wmax = wmin + 15;        // warp's max q row

    for (int kb = lo; kb < qs + AQT; kb += AKT) {
        __syncthreads();
        {
            const uint32_t* kg = Kg + (size_t)(kb + krow) * HD;
#pragma unroll
            for (int j = 0; j < 4; j++) {
                int c = kq + 4 * j;
                *(uint4*)&Ks[swz(krow, c)] = *(const uint4*)(kg + 4 * c);
            }
        }
        {
            const uint32_t* vg = Vg + (size_t)(kb + vkv) * HD + vdb * 16;
#pragma unroll
            for (int j = 0; j < 4; j++) {
                uint4 val = *(const uint4*)(vg + 4 * j);
                int d0 = vdb * 16 + 4 * j;
                int cch = vkv >> 2, co = vkv & 3;
                Vt[swz(d0 + 0, cch) + co] = val.x;
                Vt[swz(d0 + 1, cch) + co] = val.y;
                Vt[swz(d0 + 2, cch) + co] = val.z;
                Vt[swz(d0 + 3, cch) + co] = val.w;
            }
        }
        __syncthreads();

        // per-warp skip: tile fully outside [wmin-WIN, wmax] -> all P == 0
        if (kb > wmax || kb + AKT <= wmin - WIN) continue;

        float sacc[8][4];
#pragma unroll
        for (int nt = 0; nt < 8; nt++)
#pragma unroll
            for (int j = 0; j < 4; j++) sacc[nt][j] = 0.f;
#pragma unroll
        for (int i = 0; i < 4; i++) {
            uint32_t ae[4] = {qv[0][i].x, qv[1][i].x, qv[0][i].y, qv[1][i].y};
            uint32_t ao[4] = {qv[0][i].z, qv[1][i].z, qv[0][i].w, qv[1][i].w};
#pragma unroll
            for (int nt = 0; nt < 8; nt++) {
                uint4 kvv = *(const uint4*)&Ks[swz(nt * 8 + g, tg + 4 * i)];
                MMA_TF32(sacc[nt], ae, kvv.x, kvv.y);
                MMA_TF32(sacc[nt], ao, kvv.z, kvv.w);
            }
        }

        const float b0c = slope * (float)(row0 - kb) - sh0;
        const float b1c = slope * (float)(row1 - kb) - sh1;
        const int pr0 = wr + g, pr1 = wr + 8 + g;
#pragma unroll
        for (int nt = 0; nt < 8; nt++) {
            int j0 = nt * 8 + 2 * tg;
            int d00 = row0 - (kb + j0);
            int d10 = row1 - (kb + j0);
            float a00 = fmaf(sacc[nt][0], 0.125f, fmaf(-slope, (float)j0, b0c));
            float a01 = fmaf(sacc[nt][1], 0.125f, fmaf(-slope, (float)(j0 + 1), b0c));
            float a10 = fmaf(sacc[nt][2], 0.125f, fmaf(-slope, (float)j0, b1c));
            float a11 = fmaf(sacc[nt][3], 0.125f, fmaf(-slope, (float)(j0 + 1), b1c));
            uint32_t p00 = (d00 >= 0 && d00 <= WIN) ? f2tf(__expf(a00)) : 0u;
            uint32_t p01 = (d00 >= 1 && d00 <= WIN + 1) ? f2tf(__expf(a01)) : 0u;
            uint32_t p10 = (d10 >= 0 && d10 <= WIN) ? f2tf(__expf(a10)) : 0u;
            uint32_t p11 = (d10 >= 1 && d10 <= WIN + 1) ? f2tf(__expf(a11)) : 0u;
            l0 += __uint_as_float(p00) + __uint_as_float(p01);
            l1 += __uint_as_float(p10) + __uint_as_float(p11);
            int ch = j0 >> 2, wo = j0 & 3;
            uint32_t* s0 = &Ps[swz(pr0, ch) + wo];
            s0[0] = p00; s0[1] = p01;
            uint32_t* s1 = &Ps[swz(pr1, ch) + wo];
            s1[0] = p10; s1[1] = p11;
        }
        __syncwarp();

#pragma unroll
        for (int i = 0; i < 4; i++) {
            uint4 pa0 = *(const uint4*)&Ps[swz(pr0, tg + 4 * i)];
            uint4 pa1 = *(const uint4*)&Ps[swz(pr1, tg + 4 * i)];
            uint32_t ae[4] = {pa0.x, pa1.x, pa0.y, pa1.y};
            uint32_t ao[4] = {pa0.z, pa1.z, pa0.w, pa1.w};
#pragma unroll
            for (int nt = 0; nt < 8; nt++) {
                uint4 vv = *(const uint4*)&Vt[swz(nt * 8 + g, tg + 4 * i)];
                MMA_TF32(oacc[nt], ae, vv.x, vv.y);
                MMA_TF32(oacc[nt], ao, vv.z, vv.w);
            }
        }
    }

    l0 += __shfl_xor_sync(0xffffffffu, l0, 1);
    l0 += __shfl_xor_sync(0xffffffffu, l0, 2);
    l1 += __shfl_xor_sync(0xffffffffu, l1, 1);
    l1 += __shfl_xor_sync(0xffffffffu, l1, 2);
    const float inv0 = 1.f / l0, inv1 = 1.f / l1;

    uint32_t* o0 = g_ot + ((size_t)b * SEQ + row0) * EMB + h * HD;
    uint32_t* o1 = g_ot + ((size_t)b * SEQ + row1) * EMB + h * HD;
#pragma unroll
    for (int nt = 0; nt < 8; nt++) {
        int col = nt * 8 + 2 * tg;
        *(uint2*)(o0 + col) = make_uint2(f2tf(oacc[nt][0] * inv0),
                                         f2tf(oacc[nt][1] * inv0));
        *(uint2*)(o1 + col) = make_uint2(f2tf(oacc[nt][2] * inv1),
                                         f2tf(oacc[nt][3] * inv1));
    }
}

// ---------------------------------------------------------------------------
extern "C" void kernel_launch(void* const* d_in, const int* in_sizes, int n_in,
                              void* d_out, int out_size)
{
    const float* x     = (const float*)d_in[0];   // [B,S,E]
    const float* w_in  = (const float*)d_in[1];   // [3E,E]
    const float* w_out = (const float*)d_in[2];   // [E,E]
    float* out = (float*)d_out;                   // [B,S,E]

    uint32_t *xa, *wi, *wo, *ot;
    cudaGetSymbolAddress((void**)&xa, g_xa);
    cudaGetSymbolAddress((void**)&wi, g_wi);
    cudaGetSymbolAddress((void**)&wo, g_wo);
    cudaGetSymbolAddress((void**)&ot, g_ot);

    static bool attr_set = false;
    if (!attr_set) {
        cudaFuncSetAttribute(attn_tc,
                             cudaFuncAttributeMaxDynamicSharedMemorySize,
                             65536);
        cudaFuncSetAttribute(qkv_gemm,
                             cudaFuncAttributeMaxDynamicSharedMemorySize,
                             GEMM_SMEM);
        cudaFuncSetAttribute(out_gemm,
                             cudaFuncAttributeMaxDynamicSharedMemorySize,
                             GEMM_SMEM);
        attr_set = true;
    }

    // 0) one-shot tf32 conversions
    {
        int nx = BATCH * SEQ * EMB;
        int ni = 3 * EMB * EMB;
        int no = EMB * EMB;
        to_tf32<<<nx / 1024, 256>>>(x, xa, nx);
        to_tf32<<<ni / 1024, 256>>>(w_in, wi, ni);
        to_tf32<<<no / 1024, 256>>>(w_out, wo, no);
    }
    // 1) QKV projection -> q/k/v [B,H,S,D] tf32
    {
        dim3 grid(3 * EMB / BN, (BATCH * SEQ) / BM);
        qkv_gemm<<<grid, 256, GEMM_SMEM>>>(xa, wi);
    }
    // 2) tensor-core sliding-window attention -> g_ot [B,S,E] tf32
    {
        dim3 grid(SEQ / AQT, NH, BATCH);
        attn_tc<<<grid, 256, 65536>>>();
    }
    // 3) Output projection
    {
        dim3 grid(EMB / BN, (BATCH * SEQ) / BM);
        out_gemm<<<grid, 256, GEMM_SMEM>>>(ot, wo, out);
    }
}

// round 15
// speedup vs baseline: 1.0252x; 1.0252x over previous
#include <cuda_runtime.h>
#include <cuda_bf16.h>
#include <math.h>
#include <stdint.h>

// Problem constants
#define BATCH 4
#define SEQ   2048
#define EMB   1024
#define NH    16
#define HD    64
#define WIN   512

// Scratch (device globals; allocation is forbidden).
__device__ uint32_t g_q[(size_t)BATCH * NH * SEQ * HD];   // [B,H,S,D] tf32
__device__ uint32_t g_k[(size_t)BATCH * NH * SEQ * HD];
__device__ uint32_t g_v[(size_t)BATCH * NH * SEQ * HD];
__device__ uint32_t g_xa[(size_t)BATCH * SEQ * EMB];      // x in tf32
__device__ uint32_t g_wi[(size_t)3 * EMB * EMB];          // w_in in tf32
__device__ uint32_t g_wo[(size_t)EMB * EMB];              // w_out in tf32
__device__ uint32_t g_ot[(size_t)BATCH * SEQ * EMB];      // attn out tf32

__device__ __forceinline__ uint32_t f2tf(float x) {
    uint32_t r;
    asm("cvt.rna.tf32.f32 %0, %1;" : "=r"(r) : "f"(x));
    return r;
}
__device__ __forceinline__ uint4 cvt4(float4 v) {
    return make_uint4(f2tf(v.x), f2tf(v.y), f2tf(v.z), f2tf(v.w));
}

__global__ __launch_bounds__(256)
void to_tf32(const float* __restrict__ in, uint32_t* __restrict__ out, int n)
{
    int i = (blockIdx.x * blockDim.x + threadIdx.x) * 4;
    if (i < n) {
        float4 v = *(const float4*)(in + i);
        *(uint4*)(out + i) = cvt4(v);
    }
}

#define MMA_TF32(c, a, b0_, b1_)                                            \
    asm volatile(                                                           \
        "mma.sync.aligned.m16n8k8.row.col.f32.tf32.tf32.f32 "               \
        "{%0,%1,%2,%3}, {%4,%5,%6,%7}, {%8,%9}, {%0,%1,%2,%3};"            \
        : "+f"((c)[0]), "+f"((c)[1]), "+f"((c)[2]), "+f"((c)[3])            \
        : "r"((a)[0]), "r"((a)[1]), "r"((a)[2]), "r"((a)[3]),               \
          "r"(b0_), "r"(b1_))

// ---------------------------------------------------------------------------
// TF32 tensor-core GEMM (NT): C[M,N] = A[M,K] * B[N,K]^T, K=1024.
// Block tile 128x128, 256 threads = 8 warps (4M x 2N), warp tile 32x64.
// R13's proven conflict-free [row][16] smem layout, but now a 6-stage x 16-k
// cp.async pipeline processing TWO k-tiles per iteration: one wait_group +
// one __syncthreads per 32 k (32 barriers total, half of R13), prefetch
// distance 4 tiles so the overwritten stage was consumed a full barrier ago.
// ---------------------------------------------------------------------------
#define BM 128
#define BN 128
#define BKK 16
#define STG 6
#define TILE_W (BM * BKK)                 // 2048 words per stage
#define SBYTES (TILE_W * 4)               // 8192 bytes per stage
#define GEMM_SMEM (STG * 2 * SBYTES)      // 98304 bytes

__device__ __forceinline__ void cp_async16(uint32_t saddr, const void* gptr) {
    asm volatile("cp.async.cg.shared.global [%0], [%1], 16;\n"
                 :: "r"(saddr), "l"(gptr));
}
#define CP_COMMIT() asm volatile("cp.async.commit_group;\n" ::: "memory")
#define CP_WAIT1()  asm volatile("cp.async.wait_group 1;\n" ::: "memory")

// One 16-k tile of warp-level compute from stage pointers P (A) / Q (B).
__device__ __forceinline__ void tile_compute(
    const uint32_t* __restrict__ P, const uint32_t* __restrict__ Q,
    float acc[2][8][4], int warpM, int warpN, int g, int tg)
{
    uint32_t a[2][2][4];   // [ks][mt][frag]
#pragma unroll
    for (int mt = 0; mt < 2; mt++) {
        int row = warpM * 32 + mt * 16 + g;
        uint4 va = *(const uint4*)(P + row * 16 + tg * 4);
        uint4 vb = *(const uint4*)(P + (row + 8) * 16 + tg * 4);
        a[0][mt][0] = va.x; a[0][mt][1] = vb.x;
        a[0][mt][2] = va.y; a[0][mt][3] = vb.y;
        a[1][mt][0] = va.z; a[1][mt][1] = vb.z;
        a[1][mt][2] = va.w; a[1][mt][3] = vb.w;
    }
#pragma unroll
    for (int nt = 0; nt < 8; nt++) {
        int col = warpN * 64 + nt * 8 + g;
        uint4 wv = *(const uint4*)(Q + col * 16 + tg * 4);
        MMA_TF32(acc[0][nt], a[0][0], wv.x, wv.y);
        MMA_TF32(acc[1][nt], a[0][1], wv.x, wv.y);
        MMA_TF32(acc[0][nt], a[1][0], wv.z, wv.w);
        MMA_TF32(acc[1][nt], a[1][1], wv.z, wv.w);
    }
}

__device__ __forceinline__ void gemm_mainloop(
    const uint32_t* __restrict__ Ag, const uint32_t* __restrict__ Bg,
    uint32_t* Asb, uint32_t* Bsb,
    float acc[2][8][4],
    int tid, int warpM, int warpN, int g, int tg)
{
    const int K = EMB;
    const int r = tid >> 2;          // 0..63 (rows r, r+64)
    const int c = (tid & 3) << 2;    // 0,4,8,12

    const uint32_t* A0 = Ag + (size_t)r * K + c;
    const uint32_t* B0 = Bg + (size_t)r * K + c;
    const uint32_t* A1 = A0 + (size_t)64 * K;
    const uint32_t* B1 = B0 + (size_t)64 * K;

    const uint32_t a_st = (uint32_t)__cvta_generic_to_shared(Asb + r * 16 + c);
    const uint32_t b_st = (uint32_t)__cvta_generic_to_shared(Bsb + r * 16 + c);
    const uint32_t a_hi = a_st + STG * SBYTES;
    const uint32_t b_hi = b_st + STG * SBYTES;

    // prologue: tiles 0..3 into stages 0..3; groups {0,1} and {2,3}
#pragma unroll
    for (int p = 0; p < 4; p++) {
        cp_async16(a_st + p * SBYTES,        A0 + p * 16);
        cp_async16(a_st + p * SBYTES + 4096, A1 + p * 16);
        cp_async16(b_st + p * SBYTES,        B0 + p * 16);
        cp_async16(b_st + p * SBYTES + 4096, B1 + p * 16);
        if (p & 1) CP_COMMIT();
    }

    uint32_t wrA = a_st + 4 * SBYTES;    // next write: stage 4 (then 0, 2, ...)
    uint32_t wrB = b_st + 4 * SBYTES;
    const uint32_t* Ast = Asb;
    const uint32_t* Bst = Bsb;
    const uint32_t* Aend = Asb + STG * TILE_W;
    const uint32_t* Bend = Bsb + STG * TILE_W;
    int kload = 64;                       // element col of tile 4

    for (int it = 0; it < 32; it++) {
        CP_WAIT1();                       // pair (2it, 2it+1) resident
        __syncthreads();

        if (it < 30) {                    // prefetch tiles 2it+4, 2it+5
            cp_async16(wrA,                 A0 + kload);
            cp_async16(wrA + 4096,          A1 + kload);
            cp_async16(wrB,                 B0 + kload);
            cp_async16(wrB + 4096,          B1 + kload);
            cp_async16(wrA + SBYTES,        A0 + kload + 16);
            cp_async16(wrA + SBYTES + 4096, A1 + kload + 16);
            cp_async16(wrB + SBYTES,        B0 + kload + 16);
            cp_async16(wrB + SBYTES + 4096, B1 + kload + 16);
            kload += 32;
            wrA += 2 * SBYTES; if (wrA >= a_hi) wrA -= STG * SBYTES;
            wrB += 2 * SBYTES; if (wrB >= b_hi) wrB -= STG * SBYTES;
        }
        CP_COMMIT();

        tile_compute(Ast, Bst, acc, warpM, warpN, g, tg);
        tile_compute(Ast + TILE_W, Bst + TILE_W, acc, warpM, warpN, g, tg);

        Ast += 2 * TILE_W; if (Ast >= Aend) Ast -= STG * TILE_W;
        Bst += 2 * TILE_W; if (Bst >= Bend) Bst -= STG * TILE_W;
    }
}

// GEMM1: qkv projection; scatter tf32 bits into g_q/g_k/g_v ([B,H,S,D])
__global__ __launch_bounds__(256, 2)
void qkv_gemm(const uint32_t* __restrict__ A,
              const uint32_t* __restrict__ B)
{
    extern __shared__ uint32_t gsm[];
    uint32_t* Asb = gsm;
    uint32_t* Bsb = gsm + STG * TILE_W;

    const int tid = threadIdx.x;
    const int m0 = blockIdx.y * BM;
    const int n0 = blockIdx.x * BN;
    const int warp = tid >> 5;
    const int warpM = warp >> 1;
    const int warpN = warp & 1;
    const int lane = tid & 31;
    const int g = lane >> 2;
    const int tg = lane & 3;

    float acc[2][8][4];
#pragma unroll
    for (int mt = 0; mt < 2; mt++)
#pragma unroll
        for (int nt = 0; nt < 8; nt++)
#pragma unroll
            for (int j = 0; j < 4; j++) acc[mt][nt][j] = 0.f;

    gemm_mainloop(A + (size_t)m0 * EMB, B + (size_t)n0 * EMB,
                  Asb, Bsb, acc, tid, warpM, warpN, g, tg);

#pragma unroll
    for (int nt = 0; nt < 8; nt++) {
        int f = n0 + warpN * 64 + nt * 8 + 2 * tg;
        int part = f >> 10;
        int e2 = f & 1023;
        int hh = e2 >> 6;
        int d0 = e2 & 63;
        uint32_t* base = (part == 0) ? g_q : (part == 1) ? g_k : g_v;
#pragma unroll
        for (int mt = 0; mt < 2; mt++) {
            int r0 = m0 + warpM * 32 + mt * 16 + g;
            {
                int bb = r0 >> 11;
                int ss = r0 & 2047;
                size_t off = ((((size_t)bb * NH + hh) * SEQ) + ss) * HD + d0;
                *(uint2*)(base + off) =
                    make_uint2(f2tf(acc[mt][nt][0]), f2tf(acc[mt][nt][1]));
            }
            {
                int r1 = r0 + 8;
                int bb = r1 >> 11;
                int ss = r1 & 2047;
                size_t off = ((((size_t)bb * NH + hh) * SEQ) + ss) * HD + d0;
                *(uint2*)(base + off) =
                    make_uint2(f2tf(acc[mt][nt][2]), f2tf(acc[mt][nt][3]));
            }
        }
    }
}

// GEMM2: output projection, plain row-major fp32 C
__global__ __launch_bounds__(256, 2)
void out_gemm(const uint32_t* __restrict__ A,
              const uint32_t* __restrict__ B,
              float* __restrict__ C)
{
    extern __shared__ uint32_t gsm[];
    uint32_t* Asb = gsm;
    uint32_t* Bsb = gsm + STG * TILE_W;

    const int tid = threadIdx.x;
    const int m0 = blockIdx.y * BM;
    const int n0 = blockIdx.x * BN;
    const int warp = tid >> 5;
    const int warpM = warp >> 1;
    const int warpN = warp & 1;
    const int lane = tid & 31;
    const int g = lane >> 2;
    const int tg = lane & 3;

    float acc[2][8][4];
#pragma unroll
    for (int mt = 0; mt < 2; mt++)
#pragma unroll
        for (int nt = 0; nt < 8; nt++)
#pragma unroll
            for (int j = 0; j < 4; j++) acc[mt][nt][j] = 0.f;

    gemm_mainloop(A + (size_t)m0 * EMB, B + (size_t)n0 * EMB,
                  Asb, Bsb, acc, tid, warpM, warpN, g, tg);

#pragma unroll
    for (int nt = 0; nt < 8; nt++) {
        int f = n0 + warpN * 64 + nt * 8 + 2 * tg;
#pragma unroll
        for (int mt = 0; mt < 2; mt++) {
            int r0 = m0 + warpM * 32 + mt * 16 + g;
            *(float2*)(C + (size_t)r0 * EMB + f) =
                make_float2(acc[mt][nt][0], acc[mt][nt][1]);
            *(float2*)(C + (size_t)(r0 + 8) * EMB + f) =
                make_float2(acc[mt][nt][2], acc[mt][nt][3]);
        }
    }
}

// ---------------------------------------------------------------------------
// Tensor-core sliding-window attention with ALiBi (R14 version: per-warp
// all-masked tile skip; exact). Grid (S/128, H, B), 8 warps; warp w owns
// q rows [16w,16w+16). KV tiles of 64. Fixed analytic softmax shift.
// ---------------------------------------------------------------------------
#define AQT 128
#define AKT 64

__device__ __forceinline__ int swz(int row, int chunk) {
    return (row << 6) + (((chunk) ^ ((row & 3) << 2)) << 2);
}

__global__ __launch_bounds__(256, 2)
void attn_tc()
{
    extern __shared__ uint32_t sm[];
    uint32_t* Ks = sm;             // [64][64] swizzled (kv-major)
    uint32_t* Vt = sm + 4096;      // [64][64] swizzled (d-major, transposed V)
    uint32_t* Ps = sm + 8192;      // [128][64] swizzled

    const int b = blockIdx.z, h = blockIdx.y;
    const int qs = blockIdx.x * AQT;
    const int t = threadIdx.x;
    const int w = t >> 5, lane = t & 31;
    const int g = lane >> 2, tg = lane & 3;
    const int wr = w * 16;

    const size_t head_off = (((size_t)b * NH + h) * SEQ) * HD;
    const uint32_t* Qg = g_q + head_off;
    const uint32_t* Kg = g_k + head_off;
    const uint32_t* Vg = g_v + head_off;

    uint4 qv[2][4];
    {
        const uint32_t* q0 = Qg + (size_t)(qs + wr + g) * HD + 4 * tg;
        const uint32_t* q1 = Qg + (size_t)(qs + wr + 8 + g) * HD + 4 * tg;
#pragma unroll
        for (int i = 0; i < 4; i++) {
            qv[0][i] = *(const uint4*)(q0 + 16 * i);
            qv[1][i] = *(const uint4*)(q1 + 16 * i);
        }
    }

    const float slope = exp2f(-(float)(h + 1) * 0.5f);
    const int row0 = qs + wr + g, row1 = row0 + 8;
    const float sh0 = slope * (float)((row0 < WIN) ? row0 : WIN);
    const float sh1 = slope * (float)((row1 < WIN) ? row1 : WIN);

    float oacc[8][4];
#pragma unroll
    for (int nt = 0; nt < 8; nt++)
#pragma unroll
        for (int j = 0; j < 4; j++) oacc[nt][j] = 0.f;
    float l0 = 0.f, l1 = 0.f;

    const int lo = (qs >= WIN) ? qs - WIN : 0;
    const int krow = t >> 2, kq = t & 3;
    const int vkv = t & 63, vdb = t >> 6;
    const int wmin = qs + wr;
    const int wmax = wmin + 15;

    for (int kb = lo; kb < qs + AQT; kb += AKT) {
        __syncthreads();
        {
            const uint32_t* kg = Kg + (size_t)(kb + krow) * HD;
#pragma unroll
            for (int j = 0; j < 4; j++) {
                int c = kq + 4 * j;
                *(uint4*)&Ks[swz(krow, c)] = *(const uint4*)(kg + 4 * c);
            }
        }
        {
            const uint32_t* vg = Vg + (size_t)(kb + vkv) * HD + vdb * 16;
#pragma unroll
            for (int j = 0; j < 4; j++) {
                uint4 val = *(const uint4*)(vg + 4 * j);
                int d0 = vdb * 16 + 4 * j;
                int cch = vkv >> 2, co = vkv & 3;
                Vt[swz(d0 + 0, cch) + co] = val.x;
                Vt[swz(d0 + 1, cch) + co] = val.y;
                Vt[swz(d0 + 2, cch) + co] = val.z;
                Vt[swz(d0 + 3, cch) + co] = val.w;
            }
        }
        __syncthreads();

        if (kb > wmax || kb + AKT <= wmin - WIN) continue;

        float sacc[8][4];
#pragma unroll
        for (int nt = 0; nt < 8; nt++)
#pragma unroll
            for (int j = 0; j < 4; j++) sacc[nt][j] = 0.f;
#pragma unroll
        for (int i = 0; i < 4; i++) {
            uint32_t ae[4] = {qv[0][i].x, qv[1][i].x, qv[0][i].y, qv[1][i].y};
            uint32_t ao[4] = {qv[0][i].z, qv[1][i].z, qv[0][i].w, qv[1][i].w};
#pragma unroll
            for (int nt = 0; nt < 8; nt++) {
                uint4 kvv = *(const uint4*)&Ks[swz(nt * 8 + g, tg + 4 * i)];
                MMA_TF32(sacc[nt], ae, kvv.x, kvv.y);
                MMA_TF32(sacc[nt], ao, kvv.z, kvv.w);
            }
        }

        const float b0c = slope * (float)(row0 - kb) - sh0;
        const float b1c = slope * (float)(row1 - kb) - sh1;
        const int pr0 = wr + g, pr1 = wr + 8 + g;
#pragma unroll
        for (int nt = 0; nt < 8; nt++) {
            int j0 = nt * 8 + 2 * tg;
            int d00 = row0 - (kb + j0);
            int d10 = row1 - (kb + j0);
            float a00 = fmaf(sacc[nt][0], 0.125f, fmaf(-slope, (float)j0, b0c));
            float a01 = fmaf(sacc[nt][1], 0.125f, fmaf(-slope, (float)(j0 + 1), b0c));
            float a10 = fmaf(sacc[nt][2], 0.125f, fmaf(-slope, (float)j0, b1c));
            float a11 = fmaf(sacc[nt][3], 0.125f, fmaf(-slope, (float)(j0 + 1), b1c));
            uint32_t p00 = (d00 >= 0 && d00 <= WIN) ? f2tf(__expf(a00)) : 0u;
            uint32_t p01 = (d00 >= 1 && d00 <= WIN + 1) ? f2tf(__expf(a01)) : 0u;
            uint32_t p10 = (d10 >= 0 && d10 <= WIN) ? f2tf(__expf(a10)) : 0u;
            uint32_t p11 = (d10 >= 1 && d10 <= WIN + 1) ? f2tf(__expf(a11)) : 0u;
            l0 += __uint_as_float(p00) + __uint_as_float(p01);
            l1 += __uint_as_float(p10) + __uint_as_float(p11);
            int ch = j0 >> 2, wo = j0 & 3;
            uint32_t* s0 = &Ps[swz(pr0, ch) + wo];
            s0[0] = p00; s0[1] = p01;
            uint32_t* s1 = &Ps[swz(pr1, ch) + wo];
            s1[0] = p10; s1[1] = p11;
        }
        __syncwarp();

#pragma unroll
        for (int i = 0; i < 4; i++) {
            uint4 pa0 = *(const uint4*)&Ps[swz(pr0, tg + 4 * i)];
            uint4 pa1 = *(const uint4*)&Ps[swz(pr1, tg + 4 * i)];
            uint32_t ae[4] = {pa0.x, pa1.x, pa0.y, pa1.y};
            uint32_t ao[4] = {pa0.z, pa1.z, pa0.w, pa1.w};
#pragma unroll
            for (int nt = 0; nt < 8; nt++) {
                uint4 vv = *(const uint4*)&Vt[swz(nt * 8 + g, tg + 4 * i)];
                MMA_TF32(oacc[nt], ae, vv.x, vv.y);
                MMA_TF32(oacc[nt], ao, vv.z, vv.w);
            }
        }
    }

    l0 += __shfl_xor_sync(0xffffffffu, l0, 1);
    l0 += __shfl_xor_sync(0xffffffffu, l0, 2);
    l1 += __shfl_xor_sync(0xffffffffu, l1, 1);
    l1 += __shfl_xor_sync(0xffffffffu, l1, 2);
    const float inv0 = 1.f / l0, inv1 = 1.f / l1;

    uint32_t* o0 = g_ot + ((size_t)b * SEQ + row0) * EMB + h * HD;
    uint32_t* o1 = g_ot + ((size_t)b * SEQ + row1) * EMB + h * HD;
#pragma unroll
    for (int nt = 0; nt < 8; nt++) {
        int col = nt * 8 + 2 * tg;
        *(uint2*)(o0 + col) = make_uint2(f2tf(oacc[nt][0] * inv0),
                                         f2tf(oacc[nt][1] * inv0));
        *(uint2*)(o1 + col) = make_uint2(f2tf(oacc[nt][2] * inv1),
                                         f2tf(oacc[nt][3] * inv1));
    }
}

// ---------------------------------------------------------------------------
extern "C" void kernel_launch(void* const* d_in, const int* in_sizes, int n_in,
                              void* d_out, int out_size)
{
    const float* x     = (const float*)d_in[0];   // [B,S,E]
    const float* w_in  = (const float*)d_in[1];   // [3E,E]
    const float* w_out = (const float*)d_in[2];   // [E,E]
    float* out = (float*)d_out;                   // [B,S,E]

    uint32_t *xa, *wi, *wo, *ot;
    cudaGetSymbolAddress((void**)&xa, g_xa);
    cudaGetSymbolAddress((void**)&wi, g_wi);
    cudaGetSymbolAddress((void**)&wo, g_wo);
    cudaGetSymbolAddress((void**)&ot, g_ot);

    static bool attr_set = false;
    if (!attr_set) {
        cudaFuncSetAttribute(attn_tc,
                             cudaFuncAttributeMaxDynamicSharedMemorySize,
                             65536);
        cudaFuncSetAttribute(qkv_gemm,
                             cudaFuncAttributeMaxDynamicSharedMemorySize,
                             GEMM_SMEM);
        cudaFuncSetAttribute(out_gemm,
                             cudaFuncAttributeMaxDynamicSharedMemorySize,
                             GEMM_SMEM);
        attr_set = true;
    }

    // 0) one-shot tf32 conversions
    {
        int nx = BATCH * SEQ * EMB;
        int ni = 3 * EMB * EMB;
        int no = EMB * EMB;
        to_tf32<<<nx / 1024, 256>>>(x, xa, nx);
        to_tf32<<<ni / 1024, 256>>>(w_in, wi, ni);
        to_tf32<<<no / 1024, 256>>>(w_out, wo, no);
    }
    // 1) QKV projection -> q/k/v [B,H,S,D] tf32
    {
        dim3 grid(3 * EMB / BN, (BATCH * SEQ) / BM);
        qkv_gemm<<<grid, 256, GEMM_SMEM>>>(xa, wi);
    }
    // 2) tensor-core sliding-window attention -> g_ot [B,S,E] tf32
    {
        dim3 grid(SEQ / AQT, NH, BATCH);
        attn_tc<<<grid, 256, 65536>>>();
    }
    // 3) Output projection
    {
        dim3 grid(EMB / BN, (BATCH * SEQ) / BM);
        out_gemm<<<grid, 256, GEMM_SMEM>>>(ot, wo, out);
    }
}

// round 17
// speedup vs baseline: 1.4434x; 1.4079x over previous
#include <cuda_runtime.h>
#include <cuda_bf16.h>
#include <cuda_fp16.h>
#include <math.h>
#include <stdint.h>

// Problem constants
#define BATCH 4
#define SEQ   2048
#define EMB   1024
#define NH    16
#define HD    64
#define WIN   512

// Scratch (device globals; allocation is forbidden).
__device__ uint32_t g_q[(size_t)BATCH * NH * SEQ * HD];   // [B,H,S,D] tf32
__device__ uint32_t g_k[(size_t)BATCH * NH * SEQ * HD];
__device__ uint32_t g_v[(size_t)BATCH * NH * SEQ * HD];
__device__ __half   g_xh[(size_t)BATCH * SEQ * EMB];      // x fp16
__device__ __half   g_wih[(size_t)3 * EMB * EMB];         // w_in fp16
__device__ __half   g_woh[(size_t)EMB * EMB];             // w_out fp16
__device__ __half   g_oh[(size_t)BATCH * SEQ * EMB];      // attn out fp16

__device__ __forceinline__ uint32_t f2tf(float x) {
    uint32_t r;
    asm("cvt.rna.tf32.f32 %0, %1;" : "=r"(r) : "f"(x));
    return r;
}
__device__ __forceinline__ uint32_t packh2(float lo, float hi) {
    uint32_t r;
    asm("cvt.rn.f16x2.f32 %0, %1, %2;" : "=r"(r) : "f"(hi), "f"(lo));
    return r;
}

// fp32 -> fp16 bulk converter
__global__ __launch_bounds__(256)
void to_f16(const float* __restrict__ in, __half* __restrict__ out, int n)
{
    int i = (blockIdx.x * blockDim.x + threadIdx.x) * 4;
    if (i < n) {
        float4 v = *(const float4*)(in + i);
        uint2 u;
        u.x = packh2(v.x, v.y);
        u.y = packh2(v.z, v.w);
        *(uint2*)(out + i) = u;
    }
}

// fp16 mma: m16n8k16, f32 accumulate
#define MMA_F16(c, a0_, a1_, a2_, a3_, b0_, b1_)                            \
    asm volatile(                                                           \
        "mma.sync.aligned.m16n8k16.row.col.f32.f16.f16.f32 "                \
        "{%0,%1,%2,%3}, {%4,%5,%6,%7}, {%8,%9}, {%0,%1,%2,%3};"            \
        : "+f"((c)[0]), "+f"((c)[1]), "+f"((c)[2]), "+f"((c)[3])            \
        : "r"(a0_), "r"(a1_), "r"(a2_), "r"(a3_), "r"(b0_), "r"(b1_))

// tf32 mma (attention)
#define MMA_TF32(c, a, b0_, b1_)                                            \
    asm volatile(                                                           \
        "mma.sync.aligned.m16n8k8.row.col.f32.tf32.tf32.f32 "               \
        "{%0,%1,%2,%3}, {%4,%5,%6,%7}, {%8,%9}, {%0,%1,%2,%3};"            \
        : "+f"((c)[0]), "+f"((c)[1]), "+f"((c)[2]), "+f"((c)[3])            \
        : "r"((a)[0]), "r"((a)[1]), "r"((a)[2]), "r"((a)[3]),               \
          "r"(b0_), "r"(b1_))

__device__ __forceinline__ void cp_async16(uint32_t saddr, const void* gptr) {
    asm volatile("cp.async.cg.shared.global [%0], [%1], 16;\n"
                 :: "r"(saddr), "l"(gptr));
}
#define CP_COMMIT() asm volatile("cp.async.commit_group;\n" ::: "memory")
#define CP_WAIT1()  asm volatile("cp.async.wait_group 1;\n" ::: "memory")

// ---------------------------------------------------------------------------
// FP16 tensor-core GEMM (NT): C[M,N] = A[M,K] * B[N,K]^T, K=1024 halves.
// Block tile 128x128, k-tile 32 halves (64B/row), 256 threads = 8 warps
// (4M x 2N), warp tile 32x64 via m16n8k16. 3-stage cp.async pipeline.
// k-permutation: thread tg owns phys halves {8tg..8tg+7} of each 32-k tile;
// one LDS.128 per row yields all fragments (A and B use the same mapping,
// so the contraction is exact). LDS.128 pattern hits 8 bank-groups x 4
// lanes = the 4-phase minimum (conflict-free).
// ---------------------------------------------------------------------------
#define BKH 32
#define HTB (128 * 64)                   // 8192 B per operand tile
#define STG 3
#define GEMM_SMEM (STG * 2 * HTB)        // 49152 B

__device__ __forceinline__ void gemm_mainloop_h(
    const __half* __restrict__ Ag, const __half* __restrict__ Bg,
    char* smem, uint32_t smem_base,
    float acc[2][8][4], int tid, int warpM, int warpN, int g, int tg)
{
    const int r = tid >> 1;              // 0..127
    const int cb = (tid & 1) * 2;        // 16B chunk base {0,2}

    const __half* Agp = Ag + (size_t)r * EMB + cb * 8;
    const __half* Bgp = Bg + (size_t)r * EMB + cb * 8;

    const uint32_t saw = smem_base + r * 64 + cb * 16;
    const uint32_t sbw = saw + STG * HTB;

    // prologue: tiles 0,1
#pragma unroll
    for (int p = 0; p < 2; p++) {
        cp_async16(saw + p * HTB,      Agp + p * BKH);
        cp_async16(saw + p * HTB + 16, Agp + p * BKH + 8);
        cp_async16(sbw + p * HTB,      Bgp + p * BKH);
        cp_async16(sbw + p * HTB + 16, Bgp + p * BKH + 8);
        CP_COMMIT();
    }

    int st = 0;
    for (int kt = 0; kt < 32; kt++) {
        CP_WAIT1();                      // tile kt resident (own portion)
        __syncthreads();                 // publish all portions

        if (kt + 2 < 32) {               // prefetch tile kt+2 (stage consumed last iter)
            int sn = st + 2; if (sn >= STG) sn -= STG;
            int ko = (kt + 2) * BKH;
            cp_async16(saw + sn * HTB,      Agp + ko);
            cp_async16(saw + sn * HTB + 16, Agp + ko + 8);
            cp_async16(sbw + sn * HTB,      Bgp + ko);
            cp_async16(sbw + sn * HTB + 16, Bgp + ko + 8);
        }
        CP_COMMIT();

        const char* Pa = smem + st * HTB;
        const char* Pb = smem + (STG + st) * HTB;

        uint4 av[2][2];                  // [mt][row g / g+8]
#pragma unroll
        for (int mt = 0; mt < 2; mt++) {
            int row = warpM * 32 + mt * 16 + g;
            av[mt][0] = *(const uint4*)(Pa + row * 64 + tg * 16);
            av[mt][1] = *(const uint4*)(Pa + (row + 8) * 64 + tg * 16);
        }
#pragma unroll
        for (int nt = 0; nt < 8; nt++) {
            int col = warpN * 64 + nt * 8 + g;
            uint4 bv = *(const uint4*)(Pb + col * 64 + tg * 16);
#pragma unroll
            for (int mt = 0; mt < 2; mt++) {
                MMA_F16(acc[mt][nt],
                        av[mt][0].x, av[mt][1].x, av[mt][0].y, av[mt][1].y,
                        bv.x, bv.y);
                MMA_F16(acc[mt][nt],
                        av[mt][0].z, av[mt][1].z, av[mt][0].w, av[mt][1].w,
                        bv.z, bv.w);
            }
        }
        st++; if (st >= STG) st = 0;
    }
}

// GEMM1: qkv projection; scatter tf32 bits into g_q/g_k/g_v ([B,H,S,D])
__global__ __launch_bounds__(256, 2)
void qkv_gemm(const __half* __restrict__ A,      // x fp16    [8192,1024]
              const __half* __restrict__ B)      // w_in fp16 [3072,1024]
{
    extern __shared__ char smem[];
    uint32_t smem_base;
    asm("{ .reg .u64 t; cvta.to.shared.u64 t, %1; cvt.u32.u64 %0, t; }"
        : "=r"(smem_base) : "l"(smem));

    const int tid = threadIdx.x;
    const int m0 = blockIdx.y * 128;
    const int n0 = blockIdx.x * 128;
    const int warp = tid >> 5;
    const int warpM = warp >> 1;
    const int warpN = warp & 1;
    const int lane = tid & 31;
    const int g = lane >> 2;
    const int tg = lane & 3;

    float acc[2][8][4];
#pragma unroll
    for (int mt = 0; mt < 2; mt++)
#pragma unroll
        for (int nt = 0; nt < 8; nt++)
#pragma unroll
            for (int j = 0; j < 4; j++) acc[mt][nt][j] = 0.f;

    gemm_mainloop_h(A + (size_t)m0 * EMB, B + (size_t)n0 * EMB,
                    smem, smem_base, acc, tid, warpM, warpN, g, tg);

#pragma unroll
    for (int nt = 0; nt < 8; nt++) {
        int f = n0 + warpN * 64 + nt * 8 + 2 * tg;
        int part = f >> 10;
        int e2 = f & 1023;
        int hh = e2 >> 6;
        int d0 = e2 & 63;
        uint32_t* base = (part == 0) ? g_q : (part == 1) ? g_k : g_v;
#pragma unroll
        for (int mt = 0; mt < 2; mt++) {
            int r0 = m0 + warpM * 32 + mt * 16 + g;
            {
                int bb = r0 >> 11;
                int ss = r0 & 2047;
                size_t off = ((((size_t)bb * NH + hh) * SEQ) + ss) * HD + d0;
                *(uint2*)(base + off) =
                    make_uint2(f2tf(acc[mt][nt][0]), f2tf(acc[mt][nt][1]));
            }
            {
                int r1 = r0 + 8;
                int bb = r1 >> 11;
                int ss = r1 & 2047;
                size_t off = ((((size_t)bb * NH + hh) * SEQ) + ss) * HD + d0;
                *(uint2*)(base + off) =
                    make_uint2(f2tf(acc[mt][nt][2]), f2tf(acc[mt][nt][3]));
            }
        }
    }
}

// GEMM2: output projection, fp32 C
__global__ __launch_bounds__(256, 2)
void out_gemm(const __half* __restrict__ A,      // g_oh fp16  [8192,1024]
              const __half* __restrict__ B,      // w_out fp16 [1024,1024]
              float* __restrict__ C)             // out [8192,1024]
{
    extern __shared__ char smem[];
    uint32_t smem_base;
    asm("{ .reg .u64 t; cvta.to.shared.u64 t, %1; cvt.u32.u64 %0, t; }"
        : "=r"(smem_base) : "l"(smem));

    const int tid = threadIdx.x;
    const int m0 = blockIdx.y * 128;
    const int n0 = blockIdx.x * 128;
    const int warp = tid >> 5;
    const int warpM = warp >> 1;
    const int warpN = warp & 1;
    const int lane = tid & 31;
    const int g = lane >> 2;
    const int tg = lane & 3;

    float acc[2][8][4];
#pragma unroll
    for (int mt = 0; mt < 2; mt++)
#pragma unroll
        for (int nt = 0; nt < 8; nt++)
#pragma unroll
            for (int j = 0; j < 4; j++) acc[mt][nt][j] = 0.f;

    gemm_mainloop_h(A + (size_t)m0 * EMB, B + (size_t)n0 * EMB,
                    smem, smem_base, acc, tid, warpM, warpN, g, tg);

#pragma unroll
    for (int nt = 0; nt < 8; nt++) {
        int f = n0 + warpN * 64 + nt * 8 + 2 * tg;
#pragma unroll
        for (int mt = 0; mt < 2; mt++) {
            int r0 = m0 + warpM * 32 + mt * 16 + g;
            *(float2*)(C + (size_t)r0 * EMB + f) =
                make_float2(acc[mt][nt][0], acc[mt][nt][1]);
            *(float2*)(C + (size_t)(r0 + 8) * EMB + f) =
                make_float2(acc[mt][nt][2], acc[mt][nt][3]);
        }
    }
}

// ---------------------------------------------------------------------------
// mma.sync TF32 flash-attention (the passing R13 kernel; epilogue now emits
// fp16 for out_gemm). Grid (S/128, H, B), 8 warps; warp w owns q rows
// [16w,16w+16). KV tiles 64. Fixed analytic softmax shift
// m = slope*min(qi,WIN): no online max, no rescaling.
// ---------------------------------------------------------------------------
#define AQT 128
#define AKT 64

__device__ __forceinline__ int swz(int row, int chunk) {
    return (row << 6) + (((chunk) ^ ((row & 3) << 2)) << 2);
}

__global__ __launch_bounds__(256, 2)
void attn_tc()
{
    extern __shared__ uint32_t sm[];
    uint32_t* Ks = sm;
    uint32_t* Vt = sm + 4096;
    uint32_t* Ps = sm + 8192;

    const int b = blockIdx.z, h = blockIdx.y;
    const int qs = blockIdx.x * AQT;
    const int t = threadIdx.x;
    const int w = t >> 5, lane = t & 31;
    const int g = lane >> 2, tg = lane & 3;
    const int wr = w * 16;

    const size_t head_off = (((size_t)b * NH + h) * SEQ) * HD;
    const uint32_t* Qg = g_q + head_off;
    const uint32_t* Kg = g_k + head_off;
    const uint32_t* Vg = g_v + head_off;

    uint4 qv[2][4];
    {
        const uint32_t* q0 = Qg + (size_t)(qs + wr + g) * HD + 4 * tg;
        const uint32_t* q1 = Qg + (size_t)(qs + wr + 8 + g) * HD + 4 * tg;
#pragma unroll
        for (int i = 0; i < 4; i++) {
            qv[0][i] = *(const uint4*)(q0 + 16 * i);
            qv[1][i] = *(const uint4*)(q1 + 16 * i);
        }
    }

    const float slope = exp2f(-(float)(h + 1) * 0.5f);
    const int row0 = qs + wr + g, row1 = row0 + 8;
    const float sh0 = slope * (float)((row0 < WIN) ? row0 : WIN);
    const float sh1 = slope * (float)((row1 < WIN) ? row1 : WIN);

    float oacc[8][4];
#pragma unroll
    for (int nt = 0; nt < 8; nt++)
#pragma unroll
        for (int j = 0; j < 4; j++) oacc[nt][j] = 0.f;
    float l0 = 0.f, l1 = 0.f;

    const int lo = (qs >= WIN) ? qs - WIN : 0;
    const int krow = t >> 2, kq = t & 3;
    const int vkv = t & 63, vdb = t >> 6;

    for (int kb = lo; kb < qs + AQT; kb += AKT) {
        __syncthreads();
        {
            const uint32_t* kg = Kg + (size_t)(kb + krow) * HD;
#pragma unroll
            for (int j = 0; j < 4; j++) {
                int c = kq + 4 * j;
                *(uint4*)&Ks[swz(krow, c)] = *(const uint4*)(kg + 4 * c);
            }
        }
        {
            const uint32_t* vg = Vg + (size_t)(kb + vkv) * HD + vdb * 16;
#pragma unroll
            for (int j = 0; j < 4; j++) {
                uint4 val = *(const uint4*)(vg + 4 * j);
                int d0 = vdb * 16 + 4 * j;
                int cch = vkv >> 2, co = vkv & 3;
                Vt[swz(d0 + 0, cch) + co] = val.x;
                Vt[swz(d0 + 1, cch) + co] = val.y;
                Vt[swz(d0 + 2, cch) + co] = val.z;
                Vt[swz(d0 + 3, cch) + co] = val.w;
            }
        }
        __syncthreads();

        float sacc[8][4];
#pragma unroll
        for (int nt = 0; nt < 8; nt++)
#pragma unroll
            for (int j = 0; j < 4; j++) sacc[nt][j] = 0.f;
#pragma unroll
        for (int i = 0; i < 4; i++) {
            uint32_t ae[4] = {qv[0][i].x, qv[1][i].x, qv[0][i].y, qv[1][i].y};
            uint32_t ao[4] = {qv[0][i].z, qv[1][i].z, qv[0][i].w, qv[1][i].w};
#pragma unroll
            for (int nt = 0; nt < 8; nt++) {
                uint4 kvv = *(const uint4*)&Ks[swz(nt * 8 + g, tg + 4 * i)];
                MMA_TF32(sacc[nt], ae, kvv.x, kvv.y);
                MMA_TF32(sacc[nt], ao, kvv.z, kvv.w);
            }
        }

        const float b0c = slope * (float)(row0 - kb) - sh0;
        const float b1c = slope * (float)(row1 - kb) - sh1;
        const int pr0 = wr + g, pr1 = wr + 8 + g;
#pragma unroll
        for (int nt = 0; nt < 8; nt++) {
            int j0 = nt * 8 + 2 * tg;
            int d00 = row0 - (kb + j0);
            int d10 = row1 - (kb + j0);
            float a00 = fmaf(sacc[nt][0], 0.125f, fmaf(-slope, (float)j0, b0c));
            float a01 = fmaf(sacc[nt][1], 0.125f, fmaf(-slope, (float)(j0 + 1), b0c));
            float a10 = fmaf(sacc[nt][2], 0.125f, fmaf(-slope, (float)j0, b1c));
            float a11 = fmaf(sacc[nt][3], 0.125f, fmaf(-slope, (float)(j0 + 1), b1c));
            uint32_t p00 = (d00 >= 0 && d00 <= WIN) ? f2tf(__expf(a00)) : 0u;
            uint32_t p01 = (d00 >= 1 && d00 <= WIN + 1) ? f2tf(__expf(a01)) : 0u;
            uint32_t p10 = (d10 >= 0 && d10 <= WIN) ? f2tf(__expf(a10)) : 0u;
            uint32_t p11 = (d10 >= 1 && d10 <= WIN + 1) ? f2tf(__expf(a11)) : 0u;
            l0 += __uint_as_float(p00) + __uint_as_float(p01);
            l1 += __uint_as_float(p10) + __uint_as_float(p11);
            int ch = j0 >> 2, wo = j0 & 3;
            uint32_t* s0 = &Ps[swz(pr0, ch) + wo];
            s0[0] = p00; s0[1] = p01;
            uint32_t* s1 = &Ps[swz(pr1, ch) + wo];
            s1[0] = p10; s1[1] = p11;
        }
        __syncwarp();

#pragma unroll
        for (int i = 0; i < 4; i++) {
            uint4 pa0 = *(const uint4*)&Ps[swz(pr0, tg + 4 * i)];
            uint4 pa1 = *(const uint4*)&Ps[swz(pr1, tg + 4 * i)];
            uint32_t ae[4] = {pa0.x, pa1.x, pa0.y, pa1.y};
            uint32_t ao[4] = {pa0.z, pa1.z, pa0.w, pa1.w};
#pragma unroll
            for (int nt = 0; nt < 8; nt++) {
                uint4 vv = *(const uint4*)&Vt[swz(nt * 8 + g, tg + 4 * i)];
                MMA_TF32(oacc[nt], ae, vv.x, vv.y);
                MMA_TF32(oacc[nt], ao, vv.z, vv.w);
            }
        }
    }

    l0 += __shfl_xor_sync(0xffffffffu, l0, 1);
    l0 += __shfl_xor_sync(0xffffffffu, l0, 2);
    l1 += __shfl_xor_sync(0xffffffffu, l1, 1);
    l1 += __shfl_xor_sync(0xffffffffu, l1, 2);
    const float inv0 = 1.f / l0, inv1 = 1.f / l1;

    // emit fp16 (packed pairs) for out_gemm's A operand
    uint32_t* o0 = (uint32_t*)(g_oh + ((size_t)b * SEQ + row0) * EMB + h * HD);
    uint32_t* o1 = (uint32_t*)(g_oh + ((size_t)b * SEQ + row1) * EMB + h * HD);
#pragma unroll
    for (int nt = 0; nt < 8; nt++) {
        int cp2 = nt * 4 + tg;           // (nt*8 + 2tg)/2
        o0[cp2] = packh2(oacc[nt][0] * inv0, oacc[nt][1] * inv0);
        o1[cp2] = packh2(oacc[nt][2] * inv1, oacc[nt][3] * inv1);
    }
}

// ---------------------------------------------------------------------------
extern "C" void kernel_launch(void* const* d_in, const int* in_sizes, int n_in,
                              void* d_out, int out_size)
{
    const float* x     = (const float*)d_in[0];   // [B,S,E]
    const float* w_in  = (const float*)d_in[1];   // [3E,E]
    const float* w_out = (const float*)d_in[2];   // [E,E]
    float* out = (float*)d_out;                   // [B,S,E]

    __half *xh, *wih, *woh, *oh;
    cudaGetSymbolAddress((void**)&xh, g_xh);
    cudaGetSymbolAddress((void**)&wih, g_wih);
    cudaGetSymbolAddress((void**)&woh, g_woh);
    cudaGetSymbolAddress((void**)&oh, g_oh);

    static bool attr_set = false;
    if (!attr_set) {
        cudaFuncSetAttribute(attn_tc,
                             cudaFuncAttributeMaxDynamicSharedMemorySize, 65536);
        cudaFuncSetAttribute(qkv_gemm,
                             cudaFuncAttributeMaxDynamicSharedMemorySize, GEMM_SMEM);
        cudaFuncSetAttribute(out_gemm,
                             cudaFuncAttributeMaxDynamicSharedMemorySize, GEMM_SMEM);
        attr_set = true;
    }

    // 0) one-shot fp16 conversions
    {
        int nx = BATCH * SEQ * EMB;
        int ni = 3 * EMB * EMB;
        int no = EMB * EMB;
        to_f16<<<nx / 1024, 256>>>(x, xh, nx);
        to_f16<<<ni / 1024, 256>>>(w_in, wih, ni);
        to_f16<<<no / 1024, 256>>>(w_out, woh, no);
    }
    // 1) QKV projection (fp16 mma) -> q/k/v [B,H,S,D] tf32
    {
        dim3 grid(3 * EMB / 128, (BATCH * SEQ) / 128);
        qkv_gemm<<<grid, 256, GEMM_SMEM>>>(xh, wih);
    }
    // 2) tf32 tensor-core sliding-window attention -> g_oh fp16
    {
        dim3 grid(SEQ / AQT, NH, BATCH);
        attn_tc<<<grid, 256, 65536>>>();
    }
    // 3) Output projection (fp16 mma)
    {
        dim3 grid(EMB / 128, (BATCH * SEQ) / 128);
        out_gemm<<<grid, 256, GEMM_SMEM>>>(oh, woh, out);
    }
}